// round 8
// baseline (speedup 1.0000x reference)
#include <cuda_runtime.h>
#include <cuda_fp16.h>
#include <cstdint>

// ======================= problem constants =======================
static constexpr int K_DIM  = 2048;
static constexpr int N_ROWS = 8192;
static constexpr int M_TOK  = 8192;
static constexpr int N_OUT  = 4096;

// ======================= GEMM tiling =============================
static constexpr int BM = 128;
static constexpr int BK = 32;                            // finer chunks
static constexpr int NCHUNK = K_DIM / BK;                // 64
static constexpr int NSTAGE = 6;
static constexpr int PREF   = 4;                         // prefetch depth
static constexpr int TILE_BYTES  = BM * BK * 2;          // 8192 (A or B half)
static constexpr int STAGE_BYTES = 2 * TILE_BYTES;       // 16384
static constexpr int SMEM_STAGE0 = 1024;
static constexpr int SMEM_TOTAL  = SMEM_STAGE0 + NSTAGE * STAGE_BYTES;  // 99328

// ======================= device scratch ==========================
__device__ float  g55_partial[2048];
__device__ float  g55_wgamma;
__device__ __half g55_wbin[(size_t)N_ROWS * K_DIM];
__device__ __half g55_act [(size_t)M_TOK  * K_DIM];

struct __align__(16) H8 { __half2 a, b, c, d; };

// ======================= asm helpers =============================
__device__ __forceinline__ uint32_t smem_u32(const void* p) {
    uint32_t a;
    asm("{ .reg .u64 t; cvta.to.shared.u64 t, %1; cvt.u32.u64 %0, t; }" : "=r"(a) : "l"(p));
    return a;
}

#define CP_ASYNC16(dst_u32, src_ptr) \
    asm volatile("cp.async.cg.shared.global [%0], [%1], 16;" \
                 :: "r"(dst_u32), "l"(src_ptr) : "memory")

#define CP_ASYNC_ARRIVE(mbar) \
    asm volatile("cp.async.mbarrier.arrive.noinc.shared.b64 [%0];" \
                 :: "r"((uint32_t)(mbar)) : "memory")

#define MBARRIER_INIT(addr, count) \
    asm volatile("mbarrier.init.shared.b64 [%0], %1;" \
                 :: "r"((uint32_t)(addr)), "r"((uint32_t)(count)) : "memory")

#define MBARRIER_ARRIVE(addr) \
    asm volatile("mbarrier.arrive.shared.b64 _, [%0];" \
                 :: "r"((uint32_t)(addr)) : "memory")

#define MBARRIER_WAIT_PARITY(addr, parity) do {                                     \
    uint32_t _m = (uint32_t)(addr);                                                 \
    uint32_t _p = (uint32_t)(parity);                                               \
    asm volatile(                                                                   \
        "{\n\t.reg .pred P1;\n\t"                                                   \
        "WAIT_LOOP_%=:\n\t"                                                         \
        "mbarrier.try_wait.parity.shared.b64 P1, [%0], %1;\n\t"                     \
        "@P1 bra.uni WAIT_DONE_%=;\n\t"                                             \
        "bra.uni WAIT_LOOP_%=;\n\t"                                                 \
        "WAIT_DONE_%=:\n\t}"                                                        \
        :: "r"(_m), "r"(_p) : "memory");                                            \
} while (0)

#define LDSM_X4(r0, r1, r2, r3, addr) \
    asm volatile("ldmatrix.sync.aligned.m8n8.x4.shared.b16 {%0,%1,%2,%3}, [%4];" \
                 : "=r"(r0), "=r"(r1), "=r"(r2), "=r"(r3) : "r"(addr))

#define MMA16816(d, a0, a1, a2, a3, b0, b1) \
    asm volatile("mma.sync.aligned.m16n8k16.row.col.f32.f16.f16.f32 " \
                 "{%0,%1,%2,%3}, {%4,%5,%6,%7}, {%8,%9}, {%0,%1,%2,%3};" \
                 : "+f"((d)[0]), "+f"((d)[1]), "+f"((d)[2]), "+f"((d)[3]) \
                 : "r"(a0), "r"(a1), "r"(a2), "r"(a3), "r"(b0), "r"(b1))

__device__ __forceinline__ float warp_sum(float v) {
#pragma unroll
    for (int o = 16; o; o >>= 1) v += __shfl_xor_sync(0xffffffffu, v, o);
    return v;
}

// packed-row address: m-row's 16B chunk ch (0..3) of a 64B logical row,
// two logical rows per 128B physical row; conflict-free for ldmatrix.
__device__ __forceinline__ uint32_t pk_addr(uint32_t base, int r, int ch) {
    const int phys = r >> 1;
    const int grp  = (((r & 1) << 2) | ch) ^ (phys & 7);
    return base + phys * 128 + (grp << 4);
}

// ======================= prep kernels (R2 proven, unchanged) ======

__global__ __launch_bounds__(256) void glu55_wabs_partial(const float* __restrict__ w) {
    const int tid = threadIdx.x;
    const float4* w4 = reinterpret_cast<const float4*>(w);
    float s = 0.0f;
    int idx = blockIdx.x * 256 + tid;
#pragma unroll
    for (int i = 0; i < 8; ++i) {
        float4 v = w4[idx + i * (2048 * 256)];
        s += fabsf(v.x) + fabsf(v.y) + fabsf(v.z) + fabsf(v.w);
    }
    s = warp_sum(s);
    __shared__ float sh[8];
    if ((tid & 31) == 0) sh[tid >> 5] = s;
    __syncthreads();
    if (tid == 0) {
        float t = 0.0f;
#pragma unroll
        for (int i = 0; i < 8; ++i) t += sh[i];
        g55_partial[blockIdx.x] = t;
    }
}

__global__ __launch_bounds__(256) void glu55_wabs_final() {
    const int tid = threadIdx.x;
    float s = 0.0f;
    for (int i = tid; i < 2048; i += 256) s += g55_partial[i];
    s = warp_sum(s);
    __shared__ float sh[8];
    if ((tid & 31) == 0) sh[tid >> 5] = s;
    __syncthreads();
    if (tid == 0) {
        float t = 0.0f;
#pragma unroll
        for (int i = 0; i < 8; ++i) t += sh[i];
        g55_wgamma = t / (float)((size_t)N_ROWS * K_DIM);
    }
}

__device__ __forceinline__ float tern1(float v, float inv) {
    float r = rintf(v * inv);
    return fminf(1.0f, fmaxf(-1.0f, r));
}

__global__ __launch_bounds__(256) void glu55_tern(const float* __restrict__ w) {
    const int gid = blockIdx.x * 256 + threadIdx.x;
    const float inv = 1.0f / (g55_wgamma + 1e-7f);
    const float4* w4 = reinterpret_cast<const float4*>(w);
    float4 a = w4[gid * 2 + 0];
    float4 b = w4[gid * 2 + 1];
    H8 o;
    o.a = __floats2half2_rn(tern1(a.x, inv), tern1(a.y, inv));
    o.b = __floats2half2_rn(tern1(a.z, inv), tern1(a.w, inv));
    o.c = __floats2half2_rn(tern1(b.x, inv), tern1(b.y, inv));
    o.d = __floats2half2_rn(tern1(b.z, inv), tern1(b.w, inv));
    reinterpret_cast<H8*>(g55_wbin)[gid] = o;
}

__global__ __launch_bounds__(256) void glu55_ln(const float* __restrict__ x) {
    const int row = blockIdx.x;
    const int tid = threadIdx.x;
    const float4* xr = reinterpret_cast<const float4*>(x + (size_t)row * K_DIM);
    float4 v0 = xr[tid * 2 + 0];
    float4 v1 = xr[tid * 2 + 1];
    float s = v0.x + v0.y + v0.z + v0.w + v1.x + v1.y + v1.z + v1.w;
    float q = v0.x * v0.x + v0.y * v0.y + v0.z * v0.z + v0.w * v0.w +
              v1.x * v1.x + v1.y * v1.y + v1.z * v1.z + v1.w * v1.w;
    s = warp_sum(s);
    q = warp_sum(q);
    __shared__ float sh[18];
    const int wid = tid >> 5, lid = tid & 31;
    if (lid == 0) { sh[wid] = s; sh[8 + wid] = q; }
    __syncthreads();
    if (tid == 0) {
        float S = 0.0f, Q = 0.0f;
#pragma unroll
        for (int i = 0; i < 8; ++i) { S += sh[i]; Q += sh[8 + i]; }
        float mu  = S * (1.0f / (float)K_DIM);
        float var = Q * (1.0f / (float)K_DIM) - mu * mu;
        sh[16] = mu;
        sh[17] = rsqrtf(var + 1e-5f);
    }
    __syncthreads();
    const float mu = sh[16], rs = sh[17];
    H8 o;
    o.a = __floats2half2_rn((v0.x - mu) * rs, (v0.y - mu) * rs);
    o.b = __floats2half2_rn((v0.z - mu) * rs, (v0.w - mu) * rs);
    o.c = __floats2half2_rn((v1.x - mu) * rs, (v1.y - mu) * rs);
    o.d = __floats2half2_rn((v1.z - mu) * rs, (v1.w - mu) * rs);
    reinterpret_cast<H8*>(g55_act)[(size_t)row * (K_DIM / 8) + tid] = o;
}

// ======================= GEMM + fused GLU ========================
// R7 elastic mbarrier pipeline, deepened: 6 stages x BK=32, prefetch 4.
// 2 CTAs/SM, 8 warps (4 wm x 2 ngrp), tile 128m x (64h+64g) B-rows.
// Stage layout: packed rows (two 64B logical rows per 128B physical row).

__global__ void __launch_bounds__(256, 2) glu55_gemm(
    const __half* __restrict__ A, const __half* __restrict__ B,
    float* __restrict__ out)
{
    extern __shared__ char smem[];
    const uint32_t sbase = smem_u32(smem);
    const uint32_t mb_full  = sbase;        // 6 x 8B
    const uint32_t mb_empty = sbase + 48;   // 6 x 8B
    const uint32_t stage0   = sbase + SMEM_STAGE0;
    const int tid  = threadIdx.x;
    const int lane = tid & 31;
    const int wid  = tid >> 5;
    const int wm   = wid & 3;
    const int ngrp = wid >> 2;
    const int mTile = blockIdx.x & 63;
    const int nTile = blockIdx.x >> 6;

    if (tid == 0) {
#pragma unroll
        for (int s = 0; s < NSTAGE; ++s) {
            MBARRIER_INIT(mb_full  + 8 * s, 256);
            MBARRIER_INIT(mb_empty + 8 * s, 8);
        }
    }
    __syncthreads();

    float ah[2][4][4], ag[2][4][4];
#pragma unroll
    for (int i = 0; i < 2; ++i)
#pragma unroll
        for (int j = 0; j < 4; ++j)
#pragma unroll
            for (int k = 0; k < 4; ++k) { ah[i][j][k] = 0.0f; ag[i][j][k] = 0.0f; }

    // ---- per-thread loader constants (4 cp.async per stage) ----
    // thread t handles logical row r = t&127 for both A and B, chunks
    // ch = (t>>7) and (t>>7)+2 (each 16B of the 64B logical row).
    const int ld_r   = tid & 127;
    const int ld_c0  = tid >> 7;           // 0 or 1
    const __half* srcA0 = A + (size_t)(mTile * BM + ld_r) * K_DIM + ld_c0 * 8;
    const size_t growB  = (size_t)(nTile * 64 + (ld_r & 63)) + ((size_t)(ld_r >> 6) << 12);
    const __half* srcB0 = B + growB * K_DIM + ld_c0 * 8;
    const uint32_t dA0 = pk_addr(0, ld_r, ld_c0);
    const uint32_t dA1 = pk_addr(0, ld_r, ld_c0 + 2);

    auto issue_stage = [&](int g) {
        const int st = g % NSTAGE;
        const int k0 = g * BK;
        const uint32_t sA = stage0 + st * STAGE_BYTES;
        const uint32_t sB = sA + TILE_BYTES;
        CP_ASYNC16(sA + dA0, srcA0 + k0);
        CP_ASYNC16(sA + dA1, srcA0 + k0 + 16);
        CP_ASYNC16(sB + dA0, srcB0 + k0);
        CP_ASYNC16(sB + dA1, srcB0 + k0 + 16);
        CP_ASYNC_ARRIVE(mb_full + 8 * st);
    };

    auto compute_stage = [&](int st) {
        const uint32_t sA = stage0 + st * STAGE_BYTES;
        const uint32_t sB = sA + TILE_BYTES;
#pragma unroll
        for (int kk = 0; kk < 2; ++kk) {
            uint32_t a[2][4];
#pragma unroll
            for (int mt = 0; mt < 2; ++mt) {
                const int row = wm * 32 + mt * 16 + (lane & 15);
                const int ch  = kk * 2 + (lane >> 4);
                LDSM_X4(a[mt][0], a[mt][1], a[mt][2], a[mt][3], pk_addr(sA, row, ch));
            }
            uint32_t bh[2][4], bg[2][4];
#pragma unroll
            for (int tp = 0; tp < 2; ++tp) {
                const int rb = ngrp * 32 + tp * 16 + ((lane >> 4) << 3) + (lane & 7);
                const int ch = kk * 2 + ((lane >> 3) & 1);
                LDSM_X4(bh[tp][0], bh[tp][1], bh[tp][2], bh[tp][3], pk_addr(sB, rb, ch));
                LDSM_X4(bg[tp][0], bg[tp][1], bg[tp][2], bg[tp][3], pk_addr(sB, rb + 64, ch));
            }
#pragma unroll
            for (int mt = 0; mt < 2; ++mt)
#pragma unroll
                for (int tp = 0; tp < 2; ++tp) {
                    MMA16816(ah[mt][2 * tp + 0], a[mt][0], a[mt][1], a[mt][2], a[mt][3], bh[tp][0], bh[tp][1]);
                    MMA16816(ah[mt][2 * tp + 1], a[mt][0], a[mt][1], a[mt][2], a[mt][3], bh[tp][2], bh[tp][3]);
                    MMA16816(ag[mt][2 * tp + 0], a[mt][0], a[mt][1], a[mt][2], a[mt][3], bg[tp][0], bg[tp][1]);
                    MMA16816(ag[mt][2 * tp + 1], a[mt][0], a[mt][1], a[mt][2], a[mt][3], bg[tp][2], bg[tp][3]);
                }
        }
    };

#pragma unroll
    for (int g = 0; g < PREF; ++g) issue_stage(g);

#pragma unroll 1
    for (int g = 0; g < NCHUNK; ++g) {
        const int st = g % NSTAGE;
        MBARRIER_WAIT_PARITY(mb_full + 8 * st, (g / NSTAGE) & 1);
        compute_stage(st);
        if (lane == 0) MBARRIER_ARRIVE(mb_empty + 8 * st);
        const int gg = g + PREF;
        if (gg < NCHUNK) {
            const int st2 = gg % NSTAGE;
            if (gg >= NSTAGE)
                MBARRIER_WAIT_PARITY(mb_empty + 8 * st2, ((gg / NSTAGE) - 1) & 1);
            issue_stage(gg);
        }
    }

    // ---- fused GLU epilogue (all in registers) ----
    const float gw = g55_wgamma;
    const int row0 = mTile * BM + wm * 32 + (lane >> 2);
    const int col0 = nTile * 64 + ngrp * 32 + 2 * (lane & 3);
#pragma unroll
    for (int mt = 0; mt < 2; ++mt)
#pragma unroll
        for (int nb = 0; nb < 4; ++nb)
#pragma unroll
            for (int hf = 0; hf < 2; ++hf) {
                const float h0 = ah[mt][nb][2 * hf + 0] * gw;
                const float h1 = ah[mt][nb][2 * hf + 1] * gw;
                const float g0 = ag[mt][nb][2 * hf + 0] * gw;
                const float g1 = ag[mt][nb][2 * hf + 1] * gw;
                float2 o;
                o.x = h0 * (g0 / (1.0f + __expf(-g0)));
                o.y = h1 * (g1 / (1.0f + __expf(-g1)));
                const int r = row0 + mt * 16 + hf * 8;
                *reinterpret_cast<float2*>(out + (size_t)r * N_OUT + col0 + nb * 8) = o;
            }
}

// ======================= host launcher ===========================

extern "C" void kernel_launch(void* const* d_in, const int* in_sizes, int n_in,
                              void* d_out, int out_size) {
    (void)in_sizes; (void)n_in; (void)out_size;
    const float* x = (const float*)d_in[0];
    const float* w = (const float*)d_in[1];
    float* out = (float*)d_out;

    void *p_wbin = nullptr, *p_act = nullptr;
    cudaGetSymbolAddress(&p_wbin, g55_wbin);
    cudaGetSymbolAddress(&p_act,  g55_act);

    glu55_wabs_partial<<<2048, 256>>>(w);
    glu55_wabs_final<<<1, 256>>>();
    glu55_tern<<<8192, 256>>>(w);
    glu55_ln<<<M_TOK, 256>>>(x);

    cudaFuncSetAttribute(glu55_gemm, cudaFuncAttributeMaxDynamicSharedMemorySize, SMEM_TOTAL);
    glu55_gemm<<<(M_TOK / BM) * (N_OUT / 64), 256, SMEM_TOTAL>>>(
        (const __half*)p_act, (const __half*)p_wbin, out);
}

// round 9
// speedup vs baseline: 1.6859x; 1.6859x over previous
#include <cuda_runtime.h>
#include <cuda_fp16.h>
#include <cstdint>

// ======================= problem constants =======================
static constexpr int K_DIM  = 2048;
static constexpr int N_ROWS = 8192;
static constexpr int M_TOK  = 8192;
static constexpr int N_OUT  = 4096;

// ======================= GEMM tiling (R7 proven) =================
static constexpr int BM = 128;
static constexpr int BK = 64;
static constexpr int NCHUNK = K_DIM / BK;               // 32
static constexpr int NSTAGE = 3;
static constexpr int TILE_BYTES  = BM * BK * 2;         // 16384
static constexpr int STAGE_BYTES = 2 * TILE_BYTES;      // 32768
static constexpr int SMEM_STAGE0 = 1024;
static constexpr int SMEM_TOTAL  = SMEM_STAGE0 + NSTAGE * STAGE_BYTES;  // 99328

// ======================= device scratch ==========================
__device__ float  g55_partial[2048];
__device__ float  g55_wgamma;
__device__ __half g55_wbin[(size_t)N_ROWS * K_DIM];
__device__ __half g55_act [(size_t)M_TOK  * K_DIM];

struct __align__(16) H8 { __half2 a, b, c, d; };

// ======================= asm helpers =============================
__device__ __forceinline__ uint32_t smem_u32(const void* p) {
    uint32_t a;
    asm("{ .reg .u64 t; cvta.to.shared.u64 t, %1; cvt.u32.u64 %0, t; }" : "=r"(a) : "l"(p));
    return a;
}

#define CP_ASYNC16(dst_u32, src_ptr) \
    asm volatile("cp.async.cg.shared.global [%0], [%1], 16;" \
                 :: "r"(dst_u32), "l"(src_ptr) : "memory")

#define CP_ASYNC_ARRIVE(mbar) \
    asm volatile("cp.async.mbarrier.arrive.noinc.shared.b64 [%0];" \
                 :: "r"((uint32_t)(mbar)) : "memory")

#define MBARRIER_INIT(addr, count) \
    asm volatile("mbarrier.init.shared.b64 [%0], %1;" \
                 :: "r"((uint32_t)(addr)), "r"((uint32_t)(count)) : "memory")

#define MBARRIER_ARRIVE(addr) \
    asm volatile("mbarrier.arrive.shared.b64 _, [%0];" \
                 :: "r"((uint32_t)(addr)) : "memory")

#define MBARRIER_WAIT_PARITY(addr, parity) do {                                     \
    uint32_t _m = (uint32_t)(addr);                                                 \
    uint32_t _p = (uint32_t)(parity);                                               \
    asm volatile(                                                                   \
        "{\n\t.reg .pred P1;\n\t"                                                   \
        "WAIT_LOOP_%=:\n\t"                                                         \
        "mbarrier.try_wait.parity.shared.b64 P1, [%0], %1;\n\t"                     \
        "@P1 bra.uni WAIT_DONE_%=;\n\t"                                             \
        "bra.uni WAIT_LOOP_%=;\n\t"                                                 \
        "WAIT_DONE_%=:\n\t}"                                                        \
        :: "r"(_m), "r"(_p) : "memory");                                            \
} while (0)

#define LDSM_X4(r0, r1, r2, r3, addr) \
    asm volatile("ldmatrix.sync.aligned.m8n8.x4.shared.b16 {%0,%1,%2,%3}, [%4];" \
                 : "=r"(r0), "=r"(r1), "=r"(r2), "=r"(r3) : "r"(addr))

#define MMA16816(d, a0, a1, a2, a3, b0, b1) \
    asm volatile("mma.sync.aligned.m16n8k16.row.col.f32.f16.f16.f32 " \
                 "{%0,%1,%2,%3}, {%4,%5,%6,%7}, {%8,%9}, {%0,%1,%2,%3};" \
                 : "+f"((d)[0]), "+f"((d)[1]), "+f"((d)[2]), "+f"((d)[3]) \
                 : "r"(a0), "r"(a1), "r"(a2), "r"(a3), "r"(b0), "r"(b1))

__device__ __forceinline__ float warp_sum(float v) {
#pragma unroll
    for (int o = 16; o; o >>= 1) v += __shfl_xor_sync(0xffffffffu, v, o);
    return v;
}

// ======================= prep kernels (R2 proven, unchanged) ======

__global__ __launch_bounds__(256) void glu55_wabs_partial(const float* __restrict__ w) {
    const int tid = threadIdx.x;
    const float4* w4 = reinterpret_cast<const float4*>(w);
    float s = 0.0f;
    int idx = blockIdx.x * 256 + tid;
#pragma unroll
    for (int i = 0; i < 8; ++i) {
        float4 v = w4[idx + i * (2048 * 256)];
        s += fabsf(v.x) + fabsf(v.y) + fabsf(v.z) + fabsf(v.w);
    }
    s = warp_sum(s);
    __shared__ float sh[8];
    if ((tid & 31) == 0) sh[tid >> 5] = s;
    __syncthreads();
    if (tid == 0) {
        float t = 0.0f;
#pragma unroll
        for (int i = 0; i < 8; ++i) t += sh[i];
        g55_partial[blockIdx.x] = t;
    }
}

__global__ __launch_bounds__(256) void glu55_wabs_final() {
    const int tid = threadIdx.x;
    float s = 0.0f;
    for (int i = tid; i < 2048; i += 256) s += g55_partial[i];
    s = warp_sum(s);
    __shared__ float sh[8];
    if ((tid & 31) == 0) sh[tid >> 5] = s;
    __syncthreads();
    if (tid == 0) {
        float t = 0.0f;
#pragma unroll
        for (int i = 0; i < 8; ++i) t += sh[i];
        g55_wgamma = t / (float)((size_t)N_ROWS * K_DIM);
    }
}

__device__ __forceinline__ float tern1(float v, float inv) {
    float r = rintf(v * inv);
    return fminf(1.0f, fmaxf(-1.0f, r));
}

__global__ __launch_bounds__(256) void glu55_tern(const float* __restrict__ w) {
    const int gid = blockIdx.x * 256 + threadIdx.x;
    const float inv = 1.0f / (g55_wgamma + 1e-7f);
    const float4* w4 = reinterpret_cast<const float4*>(w);
    float4 a = w4[gid * 2 + 0];
    float4 b = w4[gid * 2 + 1];
    H8 o;
    o.a = __floats2half2_rn(tern1(a.x, inv), tern1(a.y, inv));
    o.b = __floats2half2_rn(tern1(a.z, inv), tern1(a.w, inv));
    o.c = __floats2half2_rn(tern1(b.x, inv), tern1(b.y, inv));
    o.d = __floats2half2_rn(tern1(b.z, inv), tern1(b.w, inv));
    reinterpret_cast<H8*>(g55_wbin)[gid] = o;
}

__global__ __launch_bounds__(256) void glu55_ln(const float* __restrict__ x) {
    const int row = blockIdx.x;
    const int tid = threadIdx.x;
    const float4* xr = reinterpret_cast<const float4*>(x + (size_t)row * K_DIM);
    float4 v0 = xr[tid * 2 + 0];
    float4 v1 = xr[tid * 2 + 1];
    float s = v0.x + v0.y + v0.z + v0.w + v1.x + v1.y + v1.z + v1.w;
    float q = v0.x * v0.x + v0.y * v0.y + v0.z * v0.z + v0.w * v0.w +
              v1.x * v1.x + v1.y * v1.y + v1.z * v1.z + v1.w * v1.w;
    s = warp_sum(s);
    q = warp_sum(q);
    __shared__ float sh[18];
    const int wid = tid >> 5, lid = tid & 31;
    if (lid == 0) { sh[wid] = s; sh[8 + wid] = q; }
    __syncthreads();
    if (tid == 0) {
        float S = 0.0f, Q = 0.0f;
#pragma unroll
        for (int i = 0; i < 8; ++i) { S += sh[i]; Q += sh[8 + i]; }
        float mu  = S * (1.0f / (float)K_DIM);
        float var = Q * (1.0f / (float)K_DIM) - mu * mu;
        sh[16] = mu;
        sh[17] = rsqrtf(var + 1e-5f);
    }
    __syncthreads();
    const float mu = sh[16], rs = sh[17];
    H8 o;
    o.a = __floats2half2_rn((v0.x - mu) * rs, (v0.y - mu) * rs);
    o.b = __floats2half2_rn((v0.z - mu) * rs, (v0.w - mu) * rs);
    o.c = __floats2half2_rn((v1.x - mu) * rs, (v1.y - mu) * rs);
    o.d = __floats2half2_rn((v1.z - mu) * rs, (v1.w - mu) * rs);
    reinterpret_cast<H8*>(g55_act)[(size_t)row * (K_DIM / 8) + tid] = o;
}

// ======================= GEMM + fused GLU ========================
// R7 winner config (elastic mbarrier, 3 stages x BK=64, 2 CTAs/SM) plus
// register-fragment double buffering: load kk+1 fragments while kk's 16
// MMAs execute, hiding LDSM latency within the warp.

__global__ void __launch_bounds__(256, 2) glu55_gemm(
    const __half* __restrict__ A, const __half* __restrict__ B,
    float* __restrict__ out)
{
    extern __shared__ char smem[];
    const uint32_t sbase = smem_u32(smem);
    const uint32_t mb_full  = sbase;
    const uint32_t mb_empty = sbase + 24;
    const uint32_t stage0   = sbase + SMEM_STAGE0;
    const int tid  = threadIdx.x;
    const int lane = tid & 31;
    const int wid  = tid >> 5;
    const int wm   = wid & 3;
    const int ngrp = wid >> 2;
    const int mTile = blockIdx.x & 63;
    const int nTile = blockIdx.x >> 6;

    if (tid == 0) {
#pragma unroll
        for (int s = 0; s < NSTAGE; ++s) {
            MBARRIER_INIT(mb_full  + 8 * s, 256);
            MBARRIER_INIT(mb_empty + 8 * s, 8);
        }
    }
    __syncthreads();

    const __half* gA = A + (size_t)mTile * BM * K_DIM;

    float ah[2][4][4], ag[2][4][4];
#pragma unroll
    for (int i = 0; i < 2; ++i)
#pragma unroll
        for (int j = 0; j < 4; ++j)
#pragma unroll
            for (int k = 0; k < 4; ++k) { ah[i][j][k] = 0.0f; ag[i][j][k] = 0.0f; }

    const int ld_row = tid >> 3;
    const int ld_ch  = tid & 7;

    auto issue_stage = [&](int g) {
        const int st = g % NSTAGE;
        const int k0 = g * BK;
        const uint32_t sA = stage0 + st * STAGE_BYTES;
        const uint32_t sB = sA + TILE_BYTES;
#pragma unroll
        for (int it = 0; it < 4; ++it) {
            const int row = it * 32 + ld_row;
            const __half* src = gA + (size_t)row * K_DIM + k0 + ld_ch * 8;
            CP_ASYNC16(sA + row * 128 + ((ld_ch ^ (row & 7)) << 4), src);
        }
        const __half* gBr = B + (size_t)(nTile * 64) * K_DIM + k0;
#pragma unroll
        for (int it = 0; it < 4; ++it) {
            const int row = it * 32 + ld_row;
            const size_t grow = (size_t)(row & 63) + ((size_t)(row >> 6) << 12);
            const __half* src = gBr + grow * K_DIM + ld_ch * 8;
            CP_ASYNC16(sB + row * 128 + ((ld_ch ^ (row & 7)) << 4), src);
        }
        CP_ASYNC_ARRIVE(mb_full + 8 * st);
    };

    // per-warp constant parts of LDSM addressing
    const int a_row0 = wm * 32 + (lane & 15);          // + mt*16
    const int a_chL  = lane >> 4;                      // kk*2 + a_chL
    const int b_rb0  = ngrp * 32 + ((lane >> 4) << 3) + (lane & 7);  // + tp*16
    const int b_chL  = (lane >> 3) & 1;                // kk*2 + b_chL

    auto load_frags = [&](uint32_t sA, uint32_t sB, int kk,
                          uint32_t a[2][4], uint32_t bh[2][4], uint32_t bg[2][4]) {
#pragma unroll
        for (int mt = 0; mt < 2; ++mt) {
            const int row = a_row0 + mt * 16;
            const int ch  = kk * 2 + a_chL;
            LDSM_X4(a[mt][0], a[mt][1], a[mt][2], a[mt][3],
                    sA + row * 128 + ((ch ^ (row & 7)) << 4));
        }
#pragma unroll
        for (int tp = 0; tp < 2; ++tp) {
            const int rb = b_rb0 + tp * 16;
            const int ch = kk * 2 + b_chL;
            const uint32_t sw = ((ch ^ (rb & 7)) << 4);
            LDSM_X4(bh[tp][0], bh[tp][1], bh[tp][2], bh[tp][3], sB + rb * 128 + sw);
            LDSM_X4(bg[tp][0], bg[tp][1], bg[tp][2], bg[tp][3], sB + (rb + 64) * 128 + sw);
        }
    };

    auto do_mma = [&](uint32_t a[2][4], uint32_t bh[2][4], uint32_t bg[2][4]) {
#pragma unroll
        for (int mt = 0; mt < 2; ++mt)
#pragma unroll
            for (int tp = 0; tp < 2; ++tp) {
                MMA16816(ah[mt][2 * tp + 0], a[mt][0], a[mt][1], a[mt][2], a[mt][3], bh[tp][0], bh[tp][1]);
                MMA16816(ah[mt][2 * tp + 1], a[mt][0], a[mt][1], a[mt][2], a[mt][3], bh[tp][2], bh[tp][3]);
                MMA16816(ag[mt][2 * tp + 0], a[mt][0], a[mt][1], a[mt][2], a[mt][3], bg[tp][0], bg[tp][1]);
                MMA16816(ag[mt][2 * tp + 1], a[mt][0], a[mt][1], a[mt][2], a[mt][3], bg[tp][2], bg[tp][3]);
            }
    };

    auto compute_stage = [&](int st) {
        const uint32_t sA = stage0 + st * STAGE_BYTES;
        const uint32_t sB = sA + TILE_BYTES;
        uint32_t aF[2][2][4], bhF[2][2][4], bgF[2][2][4];
        load_frags(sA, sB, 0, aF[0], bhF[0], bgF[0]);
#pragma unroll
        for (int kk = 0; kk < 4; ++kk) {
            const int cur = kk & 1;
            if (kk < 3)
                load_frags(sA, sB, kk + 1, aF[cur ^ 1], bhF[cur ^ 1], bgF[cur ^ 1]);
            do_mma(aF[cur], bhF[cur], bgF[cur]);
        }
    };

    issue_stage(0);
    issue_stage(1);

#pragma unroll 1
    for (int g = 0; g < NCHUNK; ++g) {
        const int st = g % NSTAGE;
        MBARRIER_WAIT_PARITY(mb_full + 8 * st, (g / NSTAGE) & 1);
        compute_stage(st);
        if (lane == 0) MBARRIER_ARRIVE(mb_empty + 8 * st);
        const int gg = g + 2;
        if (gg < NCHUNK) {
            const int st2 = gg % NSTAGE;
            if (gg >= NSTAGE)
                MBARRIER_WAIT_PARITY(mb_empty + 8 * st2, ((gg / NSTAGE) - 1) & 1);
            issue_stage(gg);
        }
    }

    // ---- fused GLU epilogue (all in registers) ----
    const float gw = g55_wgamma;
    const int row0 = mTile * BM + wm * 32 + (lane >> 2);
    const int col0 = nTile * 64 + ngrp * 32 + 2 * (lane & 3);
#pragma unroll
    for (int mt = 0; mt < 2; ++mt)
#pragma unroll
        for (int nb = 0; nb < 4; ++nb)
#pragma unroll
            for (int hf = 0; hf < 2; ++hf) {
                const float h0 = ah[mt][nb][2 * hf + 0] * gw;
                const float h1 = ah[mt][nb][2 * hf + 1] * gw;
                const float g0 = ag[mt][nb][2 * hf + 0] * gw;
                const float g1 = ag[mt][nb][2 * hf + 1] * gw;
                float2 o;
                o.x = h0 * (g0 / (1.0f + __expf(-g0)));
                o.y = h1 * (g1 / (1.0f + __expf(-g1)));
                const int r = row0 + mt * 16 + hf * 8;
                *reinterpret_cast<float2*>(out + (size_t)r * N_OUT + col0 + nb * 8) = o;
            }
}

// ======================= host launcher ===========================

extern "C" void kernel_launch(void* const* d_in, const int* in_sizes, int n_in,
                              void* d_out, int out_size) {
    (void)in_sizes; (void)n_in; (void)out_size;
    const float* x = (const float*)d_in[0];
    const float* w = (const float*)d_in[1];
    float* out = (float*)d_out;

    void *p_wbin = nullptr, *p_act = nullptr;
    cudaGetSymbolAddress(&p_wbin, g55_wbin);
    cudaGetSymbolAddress(&p_act,  g55_act);

    glu55_wabs_partial<<<2048, 256>>>(w);
    glu55_wabs_final<<<1, 256>>>();
    glu55_tern<<<8192, 256>>>(w);
    glu55_ln<<<M_TOK, 256>>>(x);

    cudaFuncSetAttribute(glu55_gemm, cudaFuncAttributeMaxDynamicSharedMemorySize, SMEM_TOTAL);
    glu55_gemm<<<(M_TOK / BM) * (N_OUT / 64), 256, SMEM_TOTAL>>>(
        (const __half*)p_act, (const __half*)p_wbin, out);
}

// round 10
// speedup vs baseline: 1.7370x; 1.0303x over previous
#include <cuda_runtime.h>
#include <cuda_fp16.h>
#include <cstdint>

// ======================= problem constants =======================
static constexpr int K_DIM  = 2048;
static constexpr int N_ROWS = 8192;
static constexpr int M_TOK  = 8192;
static constexpr int N_OUT  = 4096;

// ======================= GEMM tiling (R7 proven) =================
static constexpr int BM = 128;
static constexpr int BK = 64;
static constexpr int NCHUNK = K_DIM / BK;               // 32
static constexpr int NSTAGE = 3;
static constexpr int TILE_BYTES  = BM * BK * 2;         // 16384
static constexpr int STAGE_BYTES = 2 * TILE_BYTES;      // 32768
static constexpr int SMEM_STAGE0 = 1024;
static constexpr int SMEM_TOTAL  = SMEM_STAGE0 + NSTAGE * STAGE_BYTES;  // 99328

// ======================= device scratch ==========================
__device__ float  g55_partial[2048];
__device__ float  g55_wgamma;
__device__ __half g55_wbin[(size_t)N_ROWS * K_DIM];
__device__ __half g55_act [(size_t)M_TOK  * K_DIM];

struct __align__(16) H8 { __half2 a, b, c, d; };

// ======================= asm helpers =============================
__device__ __forceinline__ uint32_t smem_u32(const void* p) {
    uint32_t a;
    asm("{ .reg .u64 t; cvta.to.shared.u64 t, %1; cvt.u32.u64 %0, t; }" : "=r"(a) : "l"(p));
    return a;
}

#define CP_ASYNC16(dst_u32, src_ptr) \
    asm volatile("cp.async.cg.shared.global [%0], [%1], 16;" \
                 :: "r"(dst_u32), "l"(src_ptr) : "memory")

#define CP_ASYNC_ARRIVE(mbar) \
    asm volatile("cp.async.mbarrier.arrive.noinc.shared.b64 [%0];" \
                 :: "r"((uint32_t)(mbar)) : "memory")

#define MBARRIER_INIT(addr, count) \
    asm volatile("mbarrier.init.shared.b64 [%0], %1;" \
                 :: "r"((uint32_t)(addr)), "r"((uint32_t)(count)) : "memory")

#define MBARRIER_ARRIVE(addr) \
    asm volatile("mbarrier.arrive.shared.b64 _, [%0];" \
                 :: "r"((uint32_t)(addr)) : "memory")

#define MBARRIER_WAIT_PARITY(addr, parity) do {                                     \
    uint32_t _m = (uint32_t)(addr);                                                 \
    uint32_t _p = (uint32_t)(parity);                                               \
    asm volatile(                                                                   \
        "{\n\t.reg .pred P1;\n\t"                                                   \
        "WAIT_LOOP_%=:\n\t"                                                         \
        "mbarrier.try_wait.parity.shared.b64 P1, [%0], %1;\n\t"                     \
        "@P1 bra.uni WAIT_DONE_%=;\n\t"                                             \
        "bra.uni WAIT_LOOP_%=;\n\t"                                                 \
        "WAIT_DONE_%=:\n\t}"                                                        \
        :: "r"(_m), "r"(_p) : "memory");                                            \
} while (0)

#define LDSM_X4(r0, r1, r2, r3, addr) \
    asm volatile("ldmatrix.sync.aligned.m8n8.x4.shared.b16 {%0,%1,%2,%3}, [%4];" \
                 : "=r"(r0), "=r"(r1), "=r"(r2), "=r"(r3) : "r"(addr))

#define MMA16816(d, a0, a1, a2, a3, b0, b1) \
    asm volatile("mma.sync.aligned.m16n8k16.row.col.f32.f16.f16.f32 " \
                 "{%0,%1,%2,%3}, {%4,%5,%6,%7}, {%8,%9}, {%0,%1,%2,%3};" \
                 : "+f"((d)[0]), "+f"((d)[1]), "+f"((d)[2]), "+f"((d)[3]) \
                 : "r"(a0), "r"(a1), "r"(a2), "r"(a3), "r"(b0), "r"(b1))

__device__ __forceinline__ float warp_sum(float v) {
#pragma unroll
    for (int o = 16; o; o >>= 1) v += __shfl_xor_sync(0xffffffffu, v, o);
    return v;
}

// ======================= prep kernels ============================
// Fused launch 1: blocks [0, 8192)      -> layernorm x (R2 body, verbatim)
//                 blocks [8192, 10240)  -> |W| partial sums (R2 body, verbatim)
// The two parts are data-independent; concatenating grids overlaps their
// memory traffic instead of serializing two latency-bound kernels.

__global__ __launch_bounds__(256) void glu55_prep1(const float* __restrict__ x,
                                                   const float* __restrict__ w) {
    const int tid = threadIdx.x;
    if (blockIdx.x < 8192) {
        // ---- layernorm (identical to proven glu55_ln) ----
        const int row = blockIdx.x;
        const float4* xr = reinterpret_cast<const float4*>(x + (size_t)row * K_DIM);
        float4 v0 = xr[tid * 2 + 0];
        float4 v1 = xr[tid * 2 + 1];
        float s = v0.x + v0.y + v0.z + v0.w + v1.x + v1.y + v1.z + v1.w;
        float q = v0.x * v0.x + v0.y * v0.y + v0.z * v0.z + v0.w * v0.w +
                  v1.x * v1.x + v1.y * v1.y + v1.z * v1.z + v1.w * v1.w;
        s = warp_sum(s);
        q = warp_sum(q);
        __shared__ float sh[18];
        const int wid = tid >> 5, lid = tid & 31;
        if (lid == 0) { sh[wid] = s; sh[8 + wid] = q; }
        __syncthreads();
        if (tid == 0) {
            float S = 0.0f, Q = 0.0f;
#pragma unroll
            for (int i = 0; i < 8; ++i) { S += sh[i]; Q += sh[8 + i]; }
            float mu  = S * (1.0f / (float)K_DIM);
            float var = Q * (1.0f / (float)K_DIM) - mu * mu;
            sh[16] = mu;
            sh[17] = rsqrtf(var + 1e-5f);
        }
        __syncthreads();
        const float mu = sh[16], rs = sh[17];
        H8 o;
        o.a = __floats2half2_rn((v0.x - mu) * rs, (v0.y - mu) * rs);
        o.b = __floats2half2_rn((v0.z - mu) * rs, (v0.w - mu) * rs);
        o.c = __floats2half2_rn((v1.x - mu) * rs, (v1.y - mu) * rs);
        o.d = __floats2half2_rn((v1.z - mu) * rs, (v1.w - mu) * rs);
        reinterpret_cast<H8*>(g55_act)[(size_t)row * (K_DIM / 8) + tid] = o;
    } else {
        // ---- |W| partial sums (identical to proven glu55_wabs_partial) ----
        const int bid = blockIdx.x - 8192;
        const float4* w4 = reinterpret_cast<const float4*>(w);
        float s = 0.0f;
        int idx = bid * 256 + tid;
#pragma unroll
        for (int i = 0; i < 8; ++i) {
            float4 v = w4[idx + i * (2048 * 256)];
            s += fabsf(v.x) + fabsf(v.y) + fabsf(v.z) + fabsf(v.w);
        }
        s = warp_sum(s);
        __shared__ float sh2[8];
        if ((tid & 31) == 0) sh2[tid >> 5] = s;
        __syncthreads();
        if (tid == 0) {
            float t = 0.0f;
#pragma unroll
            for (int i = 0; i < 8; ++i) t += sh2[i];
            g55_partial[bid] = t;
        }
    }
}

__global__ __launch_bounds__(256) void glu55_wabs_final() {
    const int tid = threadIdx.x;
    float s = 0.0f;
    for (int i = tid; i < 2048; i += 256) s += g55_partial[i];
    s = warp_sum(s);
    __shared__ float sh[8];
    if ((tid & 31) == 0) sh[tid >> 5] = s;
    __syncthreads();
    if (tid == 0) {
        float t = 0.0f;
#pragma unroll
        for (int i = 0; i < 8; ++i) t += sh[i];
        g55_wgamma = t / (float)((size_t)N_ROWS * K_DIM);
    }
}

__device__ __forceinline__ float tern1(float v, float inv) {
    float r = rintf(v * inv);
    return fminf(1.0f, fmaxf(-1.0f, r));
}

__global__ __launch_bounds__(256) void glu55_tern(const float* __restrict__ w) {
    const int gid = blockIdx.x * 256 + threadIdx.x;
    const float inv = 1.0f / (g55_wgamma + 1e-7f);
    const float4* w4 = reinterpret_cast<const float4*>(w);
    float4 a = w4[gid * 2 + 0];
    float4 b = w4[gid * 2 + 1];
    H8 o;
    o.a = __floats2half2_rn(tern1(a.x, inv), tern1(a.y, inv));
    o.b = __floats2half2_rn(tern1(a.z, inv), tern1(a.w, inv));
    o.c = __floats2half2_rn(tern1(b.x, inv), tern1(b.y, inv));
    o.d = __floats2half2_rn(tern1(b.z, inv), tern1(b.w, inv));
    reinterpret_cast<H8*>(g55_wbin)[gid] = o;
}

// ======================= GEMM + fused GLU (R7 winner, verbatim) ==

__global__ void __launch_bounds__(256, 2) glu55_gemm(
    const __half* __restrict__ A, const __half* __restrict__ B,
    float* __restrict__ out)
{
    extern __shared__ char smem[];
    const uint32_t sbase = smem_u32(smem);
    const uint32_t mb_full  = sbase;        // 3 x 8B
    const uint32_t mb_empty = sbase + 24;   // 3 x 8B
    const uint32_t stage0   = sbase + SMEM_STAGE0;
    const int tid  = threadIdx.x;
    const int lane = tid & 31;
    const int wid  = tid >> 5;
    const int wm   = wid & 3;
    const int ngrp = wid >> 2;
    const int mTile = blockIdx.x & 63;
    const int nTile = blockIdx.x >> 6;

    if (tid == 0) {
#pragma unroll
        for (int s = 0; s < NSTAGE; ++s) {
            MBARRIER_INIT(mb_full  + 8 * s, 256);
            MBARRIER_INIT(mb_empty + 8 * s, 8);
        }
    }
    __syncthreads();

    const __half* gA = A + (size_t)mTile * BM * K_DIM;

    float ah[2][4][4], ag[2][4][4];
#pragma unroll
    for (int i = 0; i < 2; ++i)
#pragma unroll
        for (int j = 0; j < 4; ++j)
#pragma unroll
            for (int k = 0; k < 4; ++k) { ah[i][j][k] = 0.0f; ag[i][j][k] = 0.0f; }

    const int ld_row = tid >> 3;   // 0..31
    const int ld_ch  = tid & 7;

    auto issue_stage = [&](int g) {
        const int st = g % NSTAGE;
        const int k0 = g * BK;
        const uint32_t sA = stage0 + st * STAGE_BYTES;
        const uint32_t sB = sA + TILE_BYTES;
#pragma unroll
        for (int it = 0; it < 4; ++it) {
            const int row = it * 32 + ld_row;
            const __half* src = gA + (size_t)row * K_DIM + k0 + ld_ch * 8;
            CP_ASYNC16(sA + row * 128 + ((ld_ch ^ (row & 7)) << 4), src);
        }
        const __half* gBr = B + (size_t)(nTile * 64) * K_DIM + k0;
#pragma unroll
        for (int it = 0; it < 4; ++it) {
            const int row = it * 32 + ld_row;                   // 0..127
            const size_t grow = (size_t)(row & 63) + ((size_t)(row >> 6) << 12); // +4096 = g half
            const __half* src = gBr + grow * K_DIM + ld_ch * 8;
            CP_ASYNC16(sB + row * 128 + ((ld_ch ^ (row & 7)) << 4), src);
        }
        CP_ASYNC_ARRIVE(mb_full + 8 * st);
    };

    auto compute_stage = [&](int st) {
        const uint32_t sA = stage0 + st * STAGE_BYTES;
        const uint32_t sB = sA + TILE_BYTES;
#pragma unroll
        for (int kk = 0; kk < 4; ++kk) {
            uint32_t a[2][4];
#pragma unroll
            for (int mt = 0; mt < 2; ++mt) {
                const int row = wm * 32 + mt * 16 + (lane & 15);
                const int ch  = kk * 2 + (lane >> 4);
                LDSM_X4(a[mt][0], a[mt][1], a[mt][2], a[mt][3],
                        sA + row * 128 + ((ch ^ (row & 7)) << 4));
            }
            uint32_t bh[2][4], bg[2][4];
#pragma unroll
            for (int tp = 0; tp < 2; ++tp) {
                const int rb = ngrp * 32 + tp * 16 + ((lane >> 4) << 3) + (lane & 7);
                const int ch = kk * 2 + ((lane >> 3) & 1);
                const uint32_t sw = ((ch ^ (rb & 7)) << 4);
                LDSM_X4(bh[tp][0], bh[tp][1], bh[tp][2], bh[tp][3], sB + rb * 128 + sw);
                LDSM_X4(bg[tp][0], bg[tp][1], bg[tp][2], bg[tp][3], sB + (rb + 64) * 128 + sw);
            }
#pragma unroll
            for (int mt = 0; mt < 2; ++mt)
#pragma unroll
                for (int tp = 0; tp < 2; ++tp) {
                    MMA16816(ah[mt][2 * tp + 0], a[mt][0], a[mt][1], a[mt][2], a[mt][3], bh[tp][0], bh[tp][1]);
                    MMA16816(ah[mt][2 * tp + 1], a[mt][0], a[mt][1], a[mt][2], a[mt][3], bh[tp][2], bh[tp][3]);
                    MMA16816(ag[mt][2 * tp + 0], a[mt][0], a[mt][1], a[mt][2], a[mt][3], bg[tp][0], bg[tp][1]);
                    MMA16816(ag[mt][2 * tp + 1], a[mt][0], a[mt][1], a[mt][2], a[mt][3], bg[tp][2], bg[tp][3]);
                }
        }
    };

    issue_stage(0);
    issue_stage(1);

#pragma unroll 1
    for (int g = 0; g < NCHUNK; ++g) {
        const int st = g % NSTAGE;
        MBARRIER_WAIT_PARITY(mb_full + 8 * st, (g / NSTAGE) & 1);
        compute_stage(st);
        if (lane == 0) MBARRIER_ARRIVE(mb_empty + 8 * st);
        const int gg = g + 2;
        if (gg < NCHUNK) {
            const int st2 = gg % NSTAGE;
            if (gg >= NSTAGE)
                MBARRIER_WAIT_PARITY(mb_empty + 8 * st2, ((gg / NSTAGE) - 1) & 1);
            issue_stage(gg);
        }
    }

    // ---- fused GLU epilogue (all in registers) ----
    const float gw = g55_wgamma;
    const int row0 = mTile * BM + wm * 32 + (lane >> 2);
    const int col0 = nTile * 64 + ngrp * 32 + 2 * (lane & 3);
#pragma unroll
    for (int mt = 0; mt < 2; ++mt)
#pragma unroll
        for (int nb = 0; nb < 4; ++nb)
#pragma unroll
            for (int hf = 0; hf < 2; ++hf) {
                const float h0 = ah[mt][nb][2 * hf + 0] * gw;
                const float h1 = ah[mt][nb][2 * hf + 1] * gw;
                const float g0 = ag[mt][nb][2 * hf + 0] * gw;
                const float g1 = ag[mt][nb][2 * hf + 1] * gw;
                float2 o;
                o.x = h0 * (g0 / (1.0f + __expf(-g0)));
                o.y = h1 * (g1 / (1.0f + __expf(-g1)));
                const int r = row0 + mt * 16 + hf * 8;
                *reinterpret_cast<float2*>(out + (size_t)r * N_OUT + col0 + nb * 8) = o;
            }
}

// ======================= host launcher ===========================

extern "C" void kernel_launch(void* const* d_in, const int* in_sizes, int n_in,
                              void* d_out, int out_size) {
    (void)in_sizes; (void)n_in; (void)out_size;
    const float* x = (const float*)d_in[0];
    const float* w = (const float*)d_in[1];
    float* out = (float*)d_out;

    void *p_wbin = nullptr, *p_act = nullptr;
    cudaGetSymbolAddress(&p_wbin, g55_wbin);
    cudaGetSymbolAddress(&p_act,  g55_act);

    glu55_prep1<<<8192 + 2048, 256>>>(x, w);   // ln || wabs_partial (independent)
    glu55_wabs_final<<<1, 256>>>();
    glu55_tern<<<8192, 256>>>(w);

    cudaFuncSetAttribute(glu55_gemm, cudaFuncAttributeMaxDynamicSharedMemorySize, SMEM_TOTAL);
    glu55_gemm<<<(M_TOK / BM) * (N_OUT / 64), 256, SMEM_TOTAL>>>(
        (const __half*)p_act, (const __half*)p_wbin, out);
}

// round 11
// speedup vs baseline: 1.8077x; 1.0407x over previous
#include <cuda_runtime.h>
#include <cuda_fp16.h>
#include <cstdint>

// ======================= problem constants =======================
static constexpr int K_DIM  = 2048;
static constexpr int N_ROWS = 8192;
static constexpr int M_TOK  = 8192;
static constexpr int N_OUT  = 4096;

// ======================= GEMM tiling (R7/R10 proven) =============
static constexpr int BM = 128;
static constexpr int BK = 64;
static constexpr int NCHUNK = K_DIM / BK;               // 32
static constexpr int NSTAGE = 3;
static constexpr int TILE_BYTES  = BM * BK * 2;         // 16384
static constexpr int STAGE_BYTES = 2 * TILE_BYTES;      // 32768
static constexpr int SMEM_STAGE0 = 1024;
static constexpr int SMEM_TOTAL  = SMEM_STAGE0 + NSTAGE * STAGE_BYTES;  // 99328

// ======================= device scratch ==========================
__device__ float  g55_partial[2048];
__device__ float  g55_wgamma;
__device__ __half g55_wbin[(size_t)N_ROWS * K_DIM];
__device__ __half g55_act [(size_t)M_TOK  * K_DIM];

struct __align__(16) H8 { __half2 a, b, c, d; };

// ======================= asm helpers =============================
__device__ __forceinline__ uint32_t smem_u32(const void* p) {
    uint32_t a;
    asm("{ .reg .u64 t; cvta.to.shared.u64 t, %1; cvt.u32.u64 %0, t; }" : "=r"(a) : "l"(p));
    return a;
}

#define CP_ASYNC16(dst_u32, src_ptr) \
    asm volatile("cp.async.cg.shared.global [%0], [%1], 16;" \
                 :: "r"(dst_u32), "l"(src_ptr) : "memory")

#define CP_ASYNC_ARRIVE(mbar) \
    asm volatile("cp.async.mbarrier.arrive.noinc.shared.b64 [%0];" \
                 :: "r"((uint32_t)(mbar)) : "memory")

#define MBARRIER_INIT(addr, count) \
    asm volatile("mbarrier.init.shared.b64 [%0], %1;" \
                 :: "r"((uint32_t)(addr)), "r"((uint32_t)(count)) : "memory")

#define MBARRIER_ARRIVE(addr) \
    asm volatile("mbarrier.arrive.shared.b64 _, [%0];" \
                 :: "r"((uint32_t)(addr)) : "memory")

#define MBARRIER_WAIT_PARITY(addr, parity) do {                                     \
    uint32_t _m = (uint32_t)(addr);                                                 \
    uint32_t _p = (uint32_t)(parity);                                               \
    asm volatile(                                                                   \
        "{\n\t.reg .pred P1;\n\t"                                                   \
        "WAIT_LOOP_%=:\n\t"                                                         \
        "mbarrier.try_wait.parity.shared.b64 P1, [%0], %1;\n\t"                     \
        "@P1 bra.uni WAIT_DONE_%=;\n\t"                                             \
        "bra.uni WAIT_LOOP_%=;\n\t"                                                 \
        "WAIT_DONE_%=:\n\t}"                                                        \
        :: "r"(_m), "r"(_p) : "memory");                                            \
} while (0)

#define LDSM_X4(r0, r1, r2, r3, addr) \
    asm volatile("ldmatrix.sync.aligned.m8n8.x4.shared.b16 {%0,%1,%2,%3}, [%4];" \
                 : "=r"(r0), "=r"(r1), "=r"(r2), "=r"(r3) : "r"(addr))

#define MMA16816(d, a0, a1, a2, a3, b0, b1) \
    asm volatile("mma.sync.aligned.m16n8k16.row.col.f32.f16.f16.f32 " \
                 "{%0,%1,%2,%3}, {%4,%5,%6,%7}, {%8,%9}, {%0,%1,%2,%3};" \
                 : "+f"((d)[0]), "+f"((d)[1]), "+f"((d)[2]), "+f"((d)[3]) \
                 : "r"(a0), "r"(a1), "r"(a2), "r"(a3), "r"(b0), "r"(b1))

__device__ __forceinline__ float warp_sum(float v) {
#pragma unroll
    for (int o = 16; o; o >>= 1) v += __shfl_xor_sync(0xffffffffu, v, o);
    return v;
}

// ======================= prep kernels (R10 proven, unchanged) ====

__global__ __launch_bounds__(256) void glu55_prep1(const float* __restrict__ x,
                                                   const float* __restrict__ w) {
    const int tid = threadIdx.x;
    if (blockIdx.x < 8192) {
        const int row = blockIdx.x;
        const float4* xr = reinterpret_cast<const float4*>(x + (size_t)row * K_DIM);
        float4 v0 = xr[tid * 2 + 0];
        float4 v1 = xr[tid * 2 + 1];
        float s = v0.x + v0.y + v0.z + v0.w + v1.x + v1.y + v1.z + v1.w;
        float q = v0.x * v0.x + v0.y * v0.y + v0.z * v0.z + v0.w * v0.w +
                  v1.x * v1.x + v1.y * v1.y + v1.z * v1.z + v1.w * v1.w;
        s = warp_sum(s);
        q = warp_sum(q);
        __shared__ float sh[18];
        const int wid = tid >> 5, lid = tid & 31;
        if (lid == 0) { sh[wid] = s; sh[8 + wid] = q; }
        __syncthreads();
        if (tid == 0) {
            float S = 0.0f, Q = 0.0f;
#pragma unroll
            for (int i = 0; i < 8; ++i) { S += sh[i]; Q += sh[8 + i]; }
            float mu  = S * (1.0f / (float)K_DIM);
            float var = Q * (1.0f / (float)K_DIM) - mu * mu;
            sh[16] = mu;
            sh[17] = rsqrtf(var + 1e-5f);
        }
        __syncthreads();
        const float mu = sh[16], rs = sh[17];
        H8 o;
        o.a = __floats2half2_rn((v0.x - mu) * rs, (v0.y - mu) * rs);
        o.b = __floats2half2_rn((v0.z - mu) * rs, (v0.w - mu) * rs);
        o.c = __floats2half2_rn((v1.x - mu) * rs, (v1.y - mu) * rs);
        o.d = __floats2half2_rn((v1.z - mu) * rs, (v1.w - mu) * rs);
        reinterpret_cast<H8*>(g55_act)[(size_t)row * (K_DIM / 8) + tid] = o;
    } else {
        const int bid = blockIdx.x - 8192;
        const float4* w4 = reinterpret_cast<const float4*>(w);
        float s = 0.0f;
        int idx = bid * 256 + tid;
#pragma unroll
        for (int i = 0; i < 8; ++i) {
            float4 v = w4[idx + i * (2048 * 256)];
            s += fabsf(v.x) + fabsf(v.y) + fabsf(v.z) + fabsf(v.w);
        }
        s = warp_sum(s);
        __shared__ float sh2[8];
        if ((tid & 31) == 0) sh2[tid >> 5] = s;
        __syncthreads();
        if (tid == 0) {
            float t = 0.0f;
#pragma unroll
            for (int i = 0; i < 8; ++i) t += sh2[i];
            g55_partial[bid] = t;
        }
    }
}

__global__ __launch_bounds__(256) void glu55_wabs_final() {
    const int tid = threadIdx.x;
    float s = 0.0f;
    for (int i = tid; i < 2048; i += 256) s += g55_partial[i];
    s = warp_sum(s);
    __shared__ float sh[8];
    if ((tid & 31) == 0) sh[tid >> 5] = s;
    __syncthreads();
    if (tid == 0) {
        float t = 0.0f;
#pragma unroll
        for (int i = 0; i < 8; ++i) t += sh[i];
        g55_wgamma = t / (float)((size_t)N_ROWS * K_DIM);
    }
}

__device__ __forceinline__ float tern1(float v, float inv) {
    float r = rintf(v * inv);
    return fminf(1.0f, fmaxf(-1.0f, r));
}

__global__ __launch_bounds__(256) void glu55_tern(const float* __restrict__ w) {
    const int gid = blockIdx.x * 256 + threadIdx.x;
    const float inv = 1.0f / (g55_wgamma + 1e-7f);
    const float4* w4 = reinterpret_cast<const float4*>(w);
    float4 a = w4[gid * 2 + 0];
    float4 b = w4[gid * 2 + 1];
    H8 o;
    o.a = __floats2half2_rn(tern1(a.x, inv), tern1(a.y, inv));
    o.b = __floats2half2_rn(tern1(a.z, inv), tern1(a.w, inv));
    o.c = __floats2half2_rn(tern1(b.x, inv), tern1(b.y, inv));
    o.d = __floats2half2_rn(tern1(b.z, inv), tern1(b.w, inv));
    reinterpret_cast<H8*>(g55_wbin)[gid] = o;
}

// ======================= GEMM + fused GLU ========================
// R7/R10 pipeline with the main loop explicitly unrolled by 3 so that
// stage indices, stage base addresses, and barrier parities are
// compile-time constants (cuts ALU work competing with MMA issue).

__global__ void __launch_bounds__(256, 2) glu55_gemm(
    const __half* __restrict__ A, const __half* __restrict__ B,
    float* __restrict__ out)
{
    extern __shared__ char smem[];
    const uint32_t sbase = smem_u32(smem);
    const uint32_t mb_full  = sbase;
    const uint32_t mb_empty = sbase + 24;
    const uint32_t stage0   = sbase + SMEM_STAGE0;
    const int tid  = threadIdx.x;
    const int lane = tid & 31;
    const int wid  = tid >> 5;
    const int wm   = wid & 3;
    const int ngrp = wid >> 2;
    const int mTile = blockIdx.x & 63;
    const int nTile = blockIdx.x >> 6;

    if (tid == 0) {
#pragma unroll
        for (int s = 0; s < NSTAGE; ++s) {
            MBARRIER_INIT(mb_full  + 8 * s, 256);
            MBARRIER_INIT(mb_empty + 8 * s, 8);
        }
    }
    __syncthreads();

    const __half* gA = A + (size_t)mTile * BM * K_DIM;

    float ah[2][4][4], ag[2][4][4];
#pragma unroll
    for (int i = 0; i < 2; ++i)
#pragma unroll
        for (int j = 0; j < 4; ++j)
#pragma unroll
            for (int k = 0; k < 4; ++k) { ah[i][j][k] = 0.0f; ag[i][j][k] = 0.0f; }

    const int ld_row = tid >> 3;
    const int ld_ch  = tid & 7;

    // issue chunk g into stage st (st is a compile-time constant at call sites)
    auto issue_stage = [&](int g, int st) {
        const int k0 = g * BK;
        const uint32_t sA = stage0 + st * STAGE_BYTES;
        const uint32_t sB = sA + TILE_BYTES;
#pragma unroll
        for (int it = 0; it < 4; ++it) {
            const int row = it * 32 + ld_row;
            const __half* src = gA + (size_t)row * K_DIM + k0 + ld_ch * 8;
            CP_ASYNC16(sA + row * 128 + ((ld_ch ^ (row & 7)) << 4), src);
        }
        const __half* gBr = B + (size_t)(nTile * 64) * K_DIM + k0;
#pragma unroll
        for (int it = 0; it < 4; ++it) {
            const int row = it * 32 + ld_row;
            const size_t grow = (size_t)(row & 63) + ((size_t)(row >> 6) << 12);
            const __half* src = gBr + grow * K_DIM + ld_ch * 8;
            CP_ASYNC16(sB + row * 128 + ((ld_ch ^ (row & 7)) << 4), src);
        }
        CP_ASYNC_ARRIVE(mb_full + 8 * st);
    };

    auto compute_stage = [&](int st) {
        const uint32_t sA = stage0 + st * STAGE_BYTES;
        const uint32_t sB = sA + TILE_BYTES;
#pragma unroll
        for (int kk = 0; kk < 4; ++kk) {
            uint32_t a[2][4];
#pragma unroll
            for (int mt = 0; mt < 2; ++mt) {
                const int row = wm * 32 + mt * 16 + (lane & 15);
                const int ch  = kk * 2 + (lane >> 4);
                LDSM_X4(a[mt][0], a[mt][1], a[mt][2], a[mt][3],
                        sA + row * 128 + ((ch ^ (row & 7)) << 4));
            }
            uint32_t bh[2][4], bg[2][4];
#pragma unroll
            for (int tp = 0; tp < 2; ++tp) {
                const int rb = ngrp * 32 + tp * 16 + ((lane >> 4) << 3) + (lane & 7);
                const int ch = kk * 2 + ((lane >> 3) & 1);
                const uint32_t sw = ((ch ^ (rb & 7)) << 4);
                LDSM_X4(bh[tp][0], bh[tp][1], bh[tp][2], bh[tp][3], sB + rb * 128 + sw);
                LDSM_X4(bg[tp][0], bg[tp][1], bg[tp][2], bg[tp][3], sB + (rb + 64) * 128 + sw);
            }
#pragma unroll
            for (int mt = 0; mt < 2; ++mt)
#pragma unroll
                for (int tp = 0; tp < 2; ++tp) {
                    MMA16816(ah[mt][2 * tp + 0], a[mt][0], a[mt][1], a[mt][2], a[mt][3], bh[tp][0], bh[tp][1]);
                    MMA16816(ah[mt][2 * tp + 1], a[mt][0], a[mt][1], a[mt][2], a[mt][3], bh[tp][2], bh[tp][3]);
                    MMA16816(ag[mt][2 * tp + 0], a[mt][0], a[mt][1], a[mt][2], a[mt][3], bg[tp][0], bg[tp][1]);
                    MMA16816(ag[mt][2 * tp + 1], a[mt][0], a[mt][1], a[mt][2], a[mt][3], bg[tp][2], bg[tp][3]);
                }
        }
    };

    // one pipeline step: wait-full, compute, release, (wait-empty, issue g+2)
    auto step = [&](int g, int st, uint32_t fullPar,
                    int st2, uint32_t emptyPar, bool needEmptyWait, bool doIssue) {
        MBARRIER_WAIT_PARITY(mb_full + 8 * st, fullPar);
        compute_stage(st);
        if (lane == 0) MBARRIER_ARRIVE(mb_empty + 8 * st);
        if (doIssue) {
            if (needEmptyWait) MBARRIER_WAIT_PARITY(mb_empty + 8 * st2, emptyPar);
            issue_stage(g + 2, st2);
        }
    };

    issue_stage(0, 0);
    issue_stage(1, 1);

    // g=0,1,2 (round i=0): parities all 0; g=0 skips the empty wait (gg=2<3)
    step(0, 0, 0u, 2, 0u, false, true);
    step(1, 1, 0u, 0, 0u, true,  true);
    step(2, 2, 0u, 1, 0u, true,  true);
#pragma unroll 1
    for (int i = 1; i < 10; ++i) {
        const uint32_t p  = (uint32_t)(i & 1);
        const uint32_t pm = (uint32_t)((i - 1) & 1);
        const int g0 = 3 * i;
        step(g0 + 0, 0, p, 2, pm, true, true);   // gg=3i+2: ((gg/3)-1)&1 = (i-1)&1
        step(g0 + 1, 1, p, 0, p,  true, true);   // gg=3i+3: (i)&1
        step(g0 + 2, 2, p, 1, p,  true, true);   // gg=3i+4: (i)&1
    }
    // tail: g=30 (st 0, par (30/3)&1=0), g=31 (st 1, par (31/3)&1=0); no issues
    step(30, 0, 0u, 0, 0u, false, false);
    step(31, 1, 0u, 0, 0u, false, false);

    // ---- fused GLU epilogue (all in registers) ----
    const float gw = g55_wgamma;
    const int row0 = mTile * BM + wm * 32 + (lane >> 2);
    const int col0 = nTile * 64 + ngrp * 32 + 2 * (lane & 3);
#pragma unroll
    for (int mt = 0; mt < 2; ++mt)
#pragma unroll
        for (int nb = 0; nb < 4; ++nb)
#pragma unroll
            for (int hf = 0; hf < 2; ++hf) {
                const float h0 = ah[mt][nb][2 * hf + 0] * gw;
                const float h1 = ah[mt][nb][2 * hf + 1] * gw;
                const float g0 = ag[mt][nb][2 * hf + 0] * gw;
                const float g1 = ag[mt][nb][2 * hf + 1] * gw;
                float2 o;
                o.x = h0 * (g0 / (1.0f + __expf(-g0)));
                o.y = h1 * (g1 / (1.0f + __expf(-g1)));
                const int r = row0 + mt * 16 + hf * 8;
                *reinterpret_cast<float2*>(out + (size_t)r * N_OUT + col0 + nb * 8) = o;
            }
}

// ======================= host launcher ===========================

extern "C" void kernel_launch(void* const* d_in, const int* in_sizes, int n_in,
                              void* d_out, int out_size) {
    (void)in_sizes; (void)n_in; (void)out_size;
    const float* x = (const float*)d_in[0];
    const float* w = (const float*)d_in[1];
    float* out = (float*)d_out;

    void *p_wbin = nullptr, *p_act = nullptr;
    cudaGetSymbolAddress(&p_wbin, g55_wbin);
    cudaGetSymbolAddress(&p_act,  g55_act);

    glu55_prep1<<<8192 + 2048, 256>>>(x, w);   // ln || wabs_partial (independent)
    glu55_wabs_final<<<1, 256>>>();
    glu55_tern<<<8192, 256>>>(w);

    cudaFuncSetAttribute(glu55_gemm, cudaFuncAttributeMaxDynamicSharedMemorySize, SMEM_TOTAL);
    glu55_gemm<<<(M_TOK / BM) * (N_OUT / 64), 256, SMEM_TOTAL>>>(
        (const __half*)p_act, (const __half*)p_wbin, out);
}

// round 12
// speedup vs baseline: 1.8124x; 1.0026x over previous
#include <cuda_runtime.h>
#include <cuda_fp16.h>
#include <cstdint>

// ======================= problem constants =======================
static constexpr int K_DIM  = 2048;
static constexpr int N_ROWS = 8192;
static constexpr int M_TOK  = 8192;
static constexpr int N_OUT  = 4096;

// ======================= GEMM tiling (R11 proven) ================
static constexpr int BM = 128;
static constexpr int BK = 64;
static constexpr int NCHUNK = K_DIM / BK;               // 32
static constexpr int NSTAGE = 3;
static constexpr int TILE_BYTES  = BM * BK * 2;         // 16384
static constexpr int STAGE_BYTES = 2 * TILE_BYTES;      // 32768
static constexpr int SMEM_STAGE0 = 1024;
static constexpr int SMEM_TOTAL  = SMEM_STAGE0 + NSTAGE * STAGE_BYTES;  // 99328

// ======================= device scratch ==========================
__device__ float        g55_partial[2048];
__device__ float        g55_wgamma;
__device__ unsigned int g55_done = 0;
__device__ __half       g55_wbin[(size_t)N_ROWS * K_DIM];
__device__ __half       g55_act [(size_t)M_TOK  * K_DIM];

struct __align__(16) H8 { __half2 a, b, c, d; };

// ======================= asm helpers =============================
__device__ __forceinline__ uint32_t smem_u32(const void* p) {
    uint32_t a;
    asm("{ .reg .u64 t; cvta.to.shared.u64 t, %1; cvt.u32.u64 %0, t; }" : "=r"(a) : "l"(p));
    return a;
}

#define CP_ASYNC16(dst_u32, src_ptr) \
    asm volatile("cp.async.cg.shared.global [%0], [%1], 16;" \
                 :: "r"(dst_u32), "l"(src_ptr) : "memory")

#define CP_ASYNC_ARRIVE(mbar) \
    asm volatile("cp.async.mbarrier.arrive.noinc.shared.b64 [%0];" \
                 :: "r"((uint32_t)(mbar)) : "memory")

#define MBARRIER_INIT(addr, count) \
    asm volatile("mbarrier.init.shared.b64 [%0], %1;" \
                 :: "r"((uint32_t)(addr)), "r"((uint32_t)(count)) : "memory")

#define MBARRIER_ARRIVE(addr) \
    asm volatile("mbarrier.arrive.shared.b64 _, [%0];" \
                 :: "r"((uint32_t)(addr)) : "memory")

#define MBARRIER_WAIT_PARITY(addr, parity) do {                                     \
    uint32_t _m = (uint32_t)(addr);                                                 \
    uint32_t _p = (uint32_t)(parity);                                               \
    asm volatile(                                                                   \
        "{\n\t.reg .pred P1;\n\t"                                                   \
        "WAIT_LOOP_%=:\n\t"                                                         \
        "mbarrier.try_wait.parity.shared.b64 P1, [%0], %1;\n\t"                     \
        "@P1 bra.uni WAIT_DONE_%=;\n\t"                                             \
        "bra.uni WAIT_LOOP_%=;\n\t"                                                 \
        "WAIT_DONE_%=:\n\t}"                                                        \
        :: "r"(_m), "r"(_p) : "memory");                                            \
} while (0)

#define LDSM_X4(r0, r1, r2, r3, addr) \
    asm volatile("ldmatrix.sync.aligned.m8n8.x4.shared.b16 {%0,%1,%2,%3}, [%4];" \
                 : "=r"(r0), "=r"(r1), "=r"(r2), "=r"(r3) : "r"(addr))

#define MMA16816(d, a0, a1, a2, a3, b0, b1) \
    asm volatile("mma.sync.aligned.m16n8k16.row.col.f32.f16.f16.f32 " \
                 "{%0,%1,%2,%3}, {%4,%5,%6,%7}, {%8,%9}, {%0,%1,%2,%3};" \
                 : "+f"((d)[0]), "+f"((d)[1]), "+f"((d)[2]), "+f"((d)[3]) \
                 : "r"(a0), "r"(a1), "r"(a2), "r"(a3), "r"(b0), "r"(b1))

__device__ __forceinline__ float warp_sum(float v) {
#pragma unroll
    for (int o = 16; o; o >>= 1) v += __shfl_xor_sync(0xffffffffu, v, o);
    return v;
}

// ======================= prep kernels ============================
// prep1: blocks [0, 8192)      -> layernorm x (proven body)
//        blocks [8192, 10240)  -> |W| partial sums; the LAST W-block to
//        finish also performs the final gamma reduction (fixed order ->
//        bit-deterministic regardless of which block runs it).

__global__ __launch_bounds__(256) void glu55_prep1(const float* __restrict__ x,
                                                   const float* __restrict__ w) {
    const int tid = threadIdx.x;
    if (blockIdx.x < 8192) {
        const int row = blockIdx.x;
        const float4* xr = reinterpret_cast<const float4*>(x + (size_t)row * K_DIM);
        float4 v0 = xr[tid * 2 + 0];
        float4 v1 = xr[tid * 2 + 1];
        float s = v0.x + v0.y + v0.z + v0.w + v1.x + v1.y + v1.z + v1.w;
        float q = v0.x * v0.x + v0.y * v0.y + v0.z * v0.z + v0.w * v0.w +
                  v1.x * v1.x + v1.y * v1.y + v1.z * v1.z + v1.w * v1.w;
        s = warp_sum(s);
        q = warp_sum(q);
        __shared__ float sh[18];
        const int wid = tid >> 5, lid = tid & 31;
        if (lid == 0) { sh[wid] = s; sh[8 + wid] = q; }
        __syncthreads();
        if (tid == 0) {
            float S = 0.0f, Q = 0.0f;
#pragma unroll
            for (int i = 0; i < 8; ++i) { S += sh[i]; Q += sh[8 + i]; }
            float mu  = S * (1.0f / (float)K_DIM);
            float var = Q * (1.0f / (float)K_DIM) - mu * mu;
            sh[16] = mu;
            sh[17] = rsqrtf(var + 1e-5f);
        }
        __syncthreads();
        const float mu = sh[16], rs = sh[17];
        H8 o;
        o.a = __floats2half2_rn((v0.x - mu) * rs, (v0.y - mu) * rs);
        o.b = __floats2half2_rn((v0.z - mu) * rs, (v0.w - mu) * rs);
        o.c = __floats2half2_rn((v1.x - mu) * rs, (v1.y - mu) * rs);
        o.d = __floats2half2_rn((v1.z - mu) * rs, (v1.w - mu) * rs);
        reinterpret_cast<H8*>(g55_act)[(size_t)row * (K_DIM / 8) + tid] = o;
    } else {
        const int bid = blockIdx.x - 8192;
        const float4* w4 = reinterpret_cast<const float4*>(w);
        float s = 0.0f;
        int idx = bid * 256 + tid;
#pragma unroll
        for (int i = 0; i < 8; ++i) {
            float4 v = w4[idx + i * (2048 * 256)];
            s += fabsf(v.x) + fabsf(v.y) + fabsf(v.z) + fabsf(v.w);
        }
        s = warp_sum(s);
        __shared__ float sh2[8];
        __shared__ int   sh_last;
        if ((tid & 31) == 0) sh2[tid >> 5] = s;
        __syncthreads();
        if (tid == 0) {
            float t = 0.0f;
#pragma unroll
            for (int i = 0; i < 8; ++i) t += sh2[i];
            g55_partial[bid] = t;
            __threadfence();
            unsigned int old = atomicAdd(&g55_done, 1u);
            sh_last = (old == 2047u);
        }
        __syncthreads();
        if (sh_last) {
            // final gamma reduction (identical order to the old wabs_final)
            float r = 0.0f;
            for (int i = tid; i < 2048; i += 256) r += g55_partial[i];
            r = warp_sum(r);
            __shared__ float sh3[8];
            if ((tid & 31) == 0) sh3[tid >> 5] = r;
            __syncthreads();
            if (tid == 0) {
                float t = 0.0f;
#pragma unroll
                for (int i = 0; i < 8; ++i) t += sh3[i];
                g55_wgamma = t / (float)((size_t)N_ROWS * K_DIM);
                g55_done = 0u;          // reset for next graph replay
            }
        }
    }
}

__device__ __forceinline__ float tern1(float v, float inv) {
    float r = rintf(v * inv);
    return fminf(1.0f, fmaxf(-1.0f, r));
}

__global__ __launch_bounds__(256) void glu55_tern(const float* __restrict__ w) {
    const int gid = blockIdx.x * 256 + threadIdx.x;
    const float inv = 1.0f / (g55_wgamma + 1e-7f);
    const float4* w4 = reinterpret_cast<const float4*>(w);
    float4 a = w4[gid * 2 + 0];
    float4 b = w4[gid * 2 + 1];
    H8 o;
    o.a = __floats2half2_rn(tern1(a.x, inv), tern1(a.y, inv));
    o.b = __floats2half2_rn(tern1(a.z, inv), tern1(a.w, inv));
    o.c = __floats2half2_rn(tern1(b.x, inv), tern1(b.y, inv));
    o.d = __floats2half2_rn(tern1(b.z, inv), tern1(b.w, inv));
    reinterpret_cast<H8*>(g55_wbin)[gid] = o;
}

// ======================= GEMM + fused GLU (R11 winner) ===========

__global__ void __launch_bounds__(256, 2) glu55_gemm(
    const __half* __restrict__ A, const __half* __restrict__ B,
    float* __restrict__ out)
{
    extern __shared__ char smem[];
    const uint32_t sbase = smem_u32(smem);
    const uint32_t mb_full  = sbase;
    const uint32_t mb_empty = sbase + 24;
    const uint32_t stage0   = sbase + SMEM_STAGE0;
    const int tid  = threadIdx.x;
    const int lane = tid & 31;
    const int wid  = tid >> 5;
    const int wm   = wid & 3;
    const int ngrp = wid >> 2;
    const int mTile = blockIdx.x & 63;
    const int nTile = blockIdx.x >> 6;

    if (tid == 0) {
#pragma unroll
        for (int s = 0; s < NSTAGE; ++s) {
            MBARRIER_INIT(mb_full  + 8 * s, 256);
            MBARRIER_INIT(mb_empty + 8 * s, 8);
        }
    }
    __syncthreads();

    const __half* gA = A + (size_t)mTile * BM * K_DIM;

    float ah[2][4][4], ag[2][4][4];
#pragma unroll
    for (int i = 0; i < 2; ++i)
#pragma unroll
        for (int j = 0; j < 4; ++j)
#pragma unroll
            for (int k = 0; k < 4; ++k) { ah[i][j][k] = 0.0f; ag[i][j][k] = 0.0f; }

    const int ld_row = tid >> 3;
    const int ld_ch  = tid & 7;

    auto issue_stage = [&](int g, int st) {
        const int k0 = g * BK;
        const uint32_t sA = stage0 + st * STAGE_BYTES;
        const uint32_t sB = sA + TILE_BYTES;
#pragma unroll
        for (int it = 0; it < 4; ++it) {
            const int row = it * 32 + ld_row;
            const __half* src = gA + (size_t)row * K_DIM + k0 + ld_ch * 8;
            CP_ASYNC16(sA + row * 128 + ((ld_ch ^ (row & 7)) << 4), src);
        }
        const __half* gBr = B + (size_t)(nTile * 64) * K_DIM + k0;
#pragma unroll
        for (int it = 0; it < 4; ++it) {
            const int row = it * 32 + ld_row;
            const size_t grow = (size_t)(row & 63) + ((size_t)(row >> 6) << 12);
            const __half* src = gBr + grow * K_DIM + ld_ch * 8;
            CP_ASYNC16(sB + row * 128 + ((ld_ch ^ (row & 7)) << 4), src);
        }
        CP_ASYNC_ARRIVE(mb_full + 8 * st);
    };

    auto compute_stage = [&](int st) {
        const uint32_t sA = stage0 + st * STAGE_BYTES;
        const uint32_t sB = sA + TILE_BYTES;
#pragma unroll
        for (int kk = 0; kk < 4; ++kk) {
            uint32_t a[2][4];
#pragma unroll
            for (int mt = 0; mt < 2; ++mt) {
                const int row = wm * 32 + mt * 16 + (lane & 15);
                const int ch  = kk * 2 + (lane >> 4);
                LDSM_X4(a[mt][0], a[mt][1], a[mt][2], a[mt][3],
                        sA + row * 128 + ((ch ^ (row & 7)) << 4));
            }
            uint32_t bh[2][4], bg[2][4];
#pragma unroll
            for (int tp = 0; tp < 2; ++tp) {
                const int rb = ngrp * 32 + tp * 16 + ((lane >> 4) << 3) + (lane & 7);
                const int ch = kk * 2 + ((lane >> 3) & 1);
                const uint32_t sw = ((ch ^ (rb & 7)) << 4);
                LDSM_X4(bh[tp][0], bh[tp][1], bh[tp][2], bh[tp][3], sB + rb * 128 + sw);
                LDSM_X4(bg[tp][0], bg[tp][1], bg[tp][2], bg[tp][3], sB + (rb + 64) * 128 + sw);
            }
#pragma unroll
            for (int mt = 0; mt < 2; ++mt)
#pragma unroll
                for (int tp = 0; tp < 2; ++tp) {
                    MMA16816(ah[mt][2 * tp + 0], a[mt][0], a[mt][1], a[mt][2], a[mt][3], bh[tp][0], bh[tp][1]);
                    MMA16816(ah[mt][2 * tp + 1], a[mt][0], a[mt][1], a[mt][2], a[mt][3], bh[tp][2], bh[tp][3]);
                    MMA16816(ag[mt][2 * tp + 0], a[mt][0], a[mt][1], a[mt][2], a[mt][3], bg[tp][0], bg[tp][1]);
                    MMA16816(ag[mt][2 * tp + 1], a[mt][0], a[mt][1], a[mt][2], a[mt][3], bg[tp][2], bg[tp][3]);
                }
        }
    };

    auto step = [&](int g, int st, uint32_t fullPar,
                    int st2, uint32_t emptyPar, bool needEmptyWait, bool doIssue) {
        MBARRIER_WAIT_PARITY(mb_full + 8 * st, fullPar);
        compute_stage(st);
        if (lane == 0) MBARRIER_ARRIVE(mb_empty + 8 * st);
        if (doIssue) {
            if (needEmptyWait) MBARRIER_WAIT_PARITY(mb_empty + 8 * st2, emptyPar);
            issue_stage(g + 2, st2);
        }
    };

    issue_stage(0, 0);
    issue_stage(1, 1);

    step(0, 0, 0u, 2, 0u, false, true);
    step(1, 1, 0u, 0, 0u, true,  true);
    step(2, 2, 0u, 1, 0u, true,  true);
#pragma unroll 1
    for (int i = 1; i < 10; ++i) {
        const uint32_t p  = (uint32_t)(i & 1);
        const uint32_t pm = (uint32_t)((i - 1) & 1);
        const int g0 = 3 * i;
        step(g0 + 0, 0, p, 2, pm, true, true);
        step(g0 + 1, 1, p, 0, p,  true, true);
        step(g0 + 2, 2, p, 1, p,  true, true);
    }
    step(30, 0, 0u, 0, 0u, false, false);
    step(31, 1, 0u, 0, 0u, false, false);

    // ---- fused GLU epilogue (registers -> streaming stores) ----
    const float gw = g55_wgamma;
    const int row0 = mTile * BM + wm * 32 + (lane >> 2);
    const int col0 = nTile * 64 + ngrp * 32 + 2 * (lane & 3);
#pragma unroll
    for (int mt = 0; mt < 2; ++mt)
#pragma unroll
        for (int nb = 0; nb < 4; ++nb)
#pragma unroll
            for (int hf = 0; hf < 2; ++hf) {
                const float h0 = ah[mt][nb][2 * hf + 0] * gw;
                const float h1 = ah[mt][nb][2 * hf + 1] * gw;
                const float g0 = ag[mt][nb][2 * hf + 0] * gw;
                const float g1 = ag[mt][nb][2 * hf + 1] * gw;
                float2 o;
                o.x = h0 * (g0 / (1.0f + __expf(-g0)));
                o.y = h1 * (g1 / (1.0f + __expf(-g1)));
                const int r = row0 + mt * 16 + hf * 8;
                __stcs(reinterpret_cast<float2*>(out + (size_t)r * N_OUT + col0 + nb * 8), o);
            }
}

// ======================= host launcher ===========================

extern "C" void kernel_launch(void* const* d_in, const int* in_sizes, int n_in,
                              void* d_out, int out_size) {
    (void)in_sizes; (void)n_in; (void)out_size;
    const float* x = (const float*)d_in[0];
    const float* w = (const float*)d_in[1];
    float* out = (float*)d_out;

    void *p_wbin = nullptr, *p_act = nullptr;
    cudaGetSymbolAddress(&p_wbin, g55_wbin);
    cudaGetSymbolAddress(&p_act,  g55_act);

    glu55_prep1<<<8192 + 2048, 256>>>(x, w);   // ln || wabs (gamma fused in)
    glu55_tern<<<8192, 256>>>(w);

    cudaFuncSetAttribute(glu55_gemm, cudaFuncAttributeMaxDynamicSharedMemorySize, SMEM_TOTAL);
    glu55_gemm<<<(M_TOK / BM) * (N_OUT / 64), 256, SMEM_TOTAL>>>(
        (const __half*)p_act, (const __half*)p_wbin, out);
}